// round 8
// baseline (speedup 1.0000x reference)
#include <cuda_runtime.h>
#include <cstdint>

#define IW 320
#define IH 256
#define ND 64
#define NB 2
#define HW (IH*IW)          // 81920
#define DHW (ND*IH*IW)      // 5242880
#define CHW (3*HW)
#define ND2 (ND/2)          // 32
#define DSTRIDE (ND2*IH*IW) // offset between the two depth slices

// [side(2)][batch(2)][12: r00..r22, t0,t1,t2]
__device__ float g_mats[48];
__device__ int   g_fast;     // 1 => rot==I, t1==t2==0 for all 4 mats

// ---------------- setup: proj = src_proj @ inv(gt_proj), parallel ----------------
__global__ void setup_kernel(const float* __restrict__ lp,
                             const float* __restrict__ rp,
                             const float* __restrict__ gp) {
    __shared__ double sinv[2][16];
    __shared__ float smats[48];
    int t = threadIdx.x;

    if (t < 2) {
        double m[16];
        const float* G = gp + 16 * t;
#pragma unroll
        for (int i = 0; i < 16; i++) m[i] = (double)G[i];
        double v[16];
        v[0]  =  m[5]*m[10]*m[15] - m[5]*m[11]*m[14] - m[9]*m[6]*m[15] + m[9]*m[7]*m[14] + m[13]*m[6]*m[11] - m[13]*m[7]*m[10];
        v[4]  = -m[4]*m[10]*m[15] + m[4]*m[11]*m[14] + m[8]*m[6]*m[15] - m[8]*m[7]*m[14] - m[12]*m[6]*m[11] + m[12]*m[7]*m[10];
        v[8]  =  m[4]*m[9]*m[15]  - m[4]*m[11]*m[13] - m[8]*m[5]*m[15] + m[8]*m[7]*m[13] + m[12]*m[5]*m[11] - m[12]*m[7]*m[9];
        v[12] = -m[4]*m[9]*m[14]  + m[4]*m[10]*m[13] + m[8]*m[5]*m[14] - m[8]*m[6]*m[13] - m[12]*m[5]*m[10] + m[12]*m[6]*m[9];
        v[1]  = -m[1]*m[10]*m[15] + m[1]*m[11]*m[14] + m[9]*m[2]*m[15] - m[9]*m[3]*m[14] - m[13]*m[2]*m[11] + m[13]*m[3]*m[10];
        v[5]  =  m[0]*m[10]*m[15] - m[0]*m[11]*m[14] - m[8]*m[2]*m[15] + m[8]*m[3]*m[14] + m[12]*m[2]*m[11] - m[12]*m[3]*m[10];
        v[9]  = -m[0]*m[9]*m[15]  + m[0]*m[11]*m[13] + m[8]*m[1]*m[15] - m[8]*m[3]*m[13] - m[12]*m[1]*m[11] + m[12]*m[3]*m[9];
        v[13] =  m[0]*m[9]*m[14]  - m[0]*m[10]*m[13] - m[8]*m[1]*m[14] + m[8]*m[2]*m[13] + m[12]*m[1]*m[10] - m[12]*m[2]*m[9];
        v[2]  =  m[1]*m[6]*m[15]  - m[1]*m[7]*m[14]  - m[5]*m[2]*m[15] + m[5]*m[3]*m[14] + m[13]*m[2]*m[7]  - m[13]*m[3]*m[6];
        v[6]  = -m[0]*m[6]*m[15]  + m[0]*m[7]*m[14]  + m[4]*m[2]*m[15] - m[4]*m[3]*m[14] - m[12]*m[2]*m[7]  + m[12]*m[3]*m[6];
        v[10] =  m[0]*m[5]*m[15]  - m[0]*m[7]*m[13]  - m[4]*m[1]*m[15] + m[4]*m[3]*m[13] + m[12]*m[1]*m[7]  - m[12]*m[3]*m[5];
        v[14] = -m[0]*m[5]*m[14]  + m[0]*m[6]*m[13]  + m[4]*m[1]*m[14] - m[4]*m[2]*m[13] - m[12]*m[1]*m[6]  + m[12]*m[2]*m[5];
        v[3]  = -m[1]*m[6]*m[11]  + m[1]*m[7]*m[10]  + m[5]*m[2]*m[11] - m[5]*m[3]*m[10] - m[9]*m[2]*m[7]   + m[9]*m[3]*m[6];
        v[7]  =  m[0]*m[6]*m[11]  - m[0]*m[7]*m[10]  - m[4]*m[2]*m[11] + m[4]*m[3]*m[10] + m[8]*m[2]*m[7]   - m[8]*m[3]*m[6];
        v[11] = -m[0]*m[5]*m[11]  + m[0]*m[7]*m[9]   + m[4]*m[1]*m[11] - m[4]*m[3]*m[9]  - m[8]*m[1]*m[7]   + m[8]*m[3]*m[5];
        v[15] =  m[0]*m[5]*m[10]  - m[0]*m[6]*m[9]   - m[4]*m[1]*m[10] + m[4]*m[2]*m[9]  + m[8]*m[1]*m[6]   - m[8]*m[2]*m[5];
        double det = m[0]*v[0] + m[1]*v[4] + m[2]*v[8] + m[3]*v[12];
        double rdet = 1.0 / det;
#pragma unroll
        for (int i = 0; i < 16; i++) sinv[t][i] = v[i] * rdet;
    }
    __syncthreads();

    if (t < 48) {
        int mt = t / 12;              // 0..3 = s*2 + b
        int e  = t % 12;
        int s  = mt >> 1, b = mt & 1;
        const float* S = (s == 0 ? lp : rp) + 16 * b;
        int i = (e < 9) ? (e / 3) : (e - 9);
        int j = (e < 9) ? (e % 3) : 3;
        double acc = 0.0;
#pragma unroll
        for (int k = 0; k < 4; k++) acc += (double)S[i * 4 + k] * sinv[b][k * 4 + j];
        float f = (float)acc;
        g_mats[mt * 12 + e] = f;
        smats[mt * 12 + e]  = f;
    }
    __syncthreads();

    if (t == 0) {
        int fast = 1;
        for (int mm = 0; mm < 4; mm++) {
            const float* dd = smats + mm * 12;
            for (int i = 0; i < 3; i++)
                for (int j = 0; j < 3; j++) {
                    float want = (i == j) ? 1.0f : 0.0f;
                    if (fabsf(dd[i * 3 + j] - want) > 1e-4f) fast = 0;
                }
            if (fabsf(dd[10]) > 1e-4f || fabsf(dd[11]) > 1e-4f) fast = 0;
        }
        g_fast = fast;
    }
}

// ---------------- threefry: 4 independent chains, hand-interleaved ----------------
__device__ __forceinline__ uint32_t rotl32(uint32_t x, int d) {
    return __funnelshift_l(x, x, d);
}

// JAX partitionable threefry-2x32, key (0,1), counts (0, lo[i]); output = x0 ^ x1.
__device__ __forceinline__ void tf_uniform4(const uint32_t lo[4], float n[4]) {
    const uint32_t ks2 = 0x1BD11BDBu;
    uint32_t a0, a1, a2, a3;        // x0 lanes
    uint32_t b0, b1, b2, b3;        // x1 lanes
    a0 = 0u; b0 = lo[0] + 1u;
    a1 = 0u; b1 = lo[1] + 1u;
    a2 = 0u; b2 = lo[2] + 1u;
    a3 = 0u; b3 = lo[3] + 1u;
#define TF_R(D)                                              \
    a0 += b0; b0 = rotl32(b0, D); b0 ^= a0;                  \
    a1 += b1; b1 = rotl32(b1, D); b1 ^= a1;                  \
    a2 += b2; b2 = rotl32(b2, D); b2 ^= a2;                  \
    a3 += b3; b3 = rotl32(b3, D); b3 ^= a3;
#define TF_INJ(KA, KB)                                       \
    a0 += (KA); b0 += (KB);                                  \
    a1 += (KA); b1 += (KB);                                  \
    a2 += (KA); b2 += (KB);                                  \
    a3 += (KA); b3 += (KB);
    TF_R(13) TF_R(15) TF_R(26) TF_R(6)   TF_INJ(1u,  ks2 + 1u)
    TF_R(17) TF_R(29) TF_R(16) TF_R(24)  TF_INJ(ks2, 2u)
    TF_R(13) TF_R(15) TF_R(26) TF_R(6)   TF_INJ(0u,  1u + 3u)
    TF_R(17) TF_R(29) TF_R(16) TF_R(24)  TF_INJ(1u,  ks2 + 4u)
    TF_R(13) TF_R(15) TF_R(26) TF_R(6)   TF_INJ(ks2, 5u)
#undef TF_R
#undef TF_INJ
    uint32_t r0 = a0 ^ b0, r1 = a1 ^ b1, r2 = a2 ^ b2, r3 = a3 ^ b3;
    n[0] = __uint_as_float((r0 >> 9) | 0x3F800000u) - 1.0f;
    n[1] = __uint_as_float((r1 >> 9) | 0x3F800000u) - 1.0f;
    n[2] = __uint_as_float((r2 >> 9) | 0x3F800000u) - 1.0f;
    n[3] = __uint_as_float((r3 >> 9) | 0x3F800000u) - 1.0f;
}

// ---------------- generic-path helpers ----------------
struct BL {
    int   o00, o10, o01, o11;
    float w00, w10, w01, w11;
};

__device__ __forceinline__ BL mkbl(float px, float py) {
    float x0f = floorf(px), y0f = floorf(py);
    float wx = px - x0f, wy = py - y0f;
    float vx0 = (x0f >= 0.f        && x0f <= (float)(IW - 1)) ? 1.f : 0.f;
    float vx1 = (x0f + 1.f >= 0.f  && x0f + 1.f <= (float)(IW - 1)) ? 1.f : 0.f;
    float vy0 = (y0f >= 0.f        && y0f <= (float)(IH - 1)) ? 1.f : 0.f;
    float vy1 = (y0f + 1.f >= 0.f  && y0f + 1.f <= (float)(IH - 1)) ? 1.f : 0.f;
    int xi0 = (int)fminf(fmaxf(x0f,       0.f), (float)(IW - 1));
    int xi1 = (int)fminf(fmaxf(x0f + 1.f, 0.f), (float)(IW - 1));
    int yi0 = (int)fminf(fmaxf(y0f,       0.f), (float)(IH - 1));
    int yi1 = (int)fminf(fmaxf(y0f + 1.f, 0.f), (float)(IH - 1));
    BL b;
    b.o00 = yi0 * IW + xi0; b.o10 = yi0 * IW + xi1;
    b.o01 = yi1 * IW + xi0; b.o11 = yi1 * IW + xi1;
    b.w00 = (1.f - wx) * (1.f - wy) * vx0 * vy0;
    b.w10 = wx * (1.f - wy) * vx1 * vy0;
    b.w01 = (1.f - wx) * wy * vx0 * vy1;
    b.w11 = wx * wy * vx1 * vy1;
    return b;
}

__device__ __forceinline__ float samp(const float* __restrict__ p, const BL& b) {
    return __ldg(p + b.o00) * b.w00 + __ldg(p + b.o10) * b.w10 +
           __ldg(p + b.o01) * b.w01 + __ldg(p + b.o11) * b.w11;
}

__device__ __forceinline__ void project(const float* M, float x, float y, float depth,
                                        float& px, float& py) {
    float rx = __ldg(M+0) * x + __ldg(M+1) * y + __ldg(M+2);
    float ry = __ldg(M+3) * x + __ldg(M+4) * y + __ldg(M+5);
    float rz = __ldg(M+6) * x + __ldg(M+7) * y + __ldg(M+8);
    float zz = rz * depth + __ldg(M+11);
    bool neg = (zz <= 0.001f);
    float z  = neg ? 1.0f : zz;
    float ax = neg ? (float)IW : (rx * depth + __ldg(M+9));
    float ay = neg ? (float)IH : (ry * depth + __ldg(M+10));
    px = ax / z;
    py = ay / z;
}

// ---------------- fast-path helper: 2-tap horizontal ----------------
struct BLX { int o0, o1; float w0, w1; };

__device__ __forceinline__ BLX mkblx(float px) {
    float xf = floorf(px);
    float wx = px - xf;
    float v0 = (xf >= 0.f  && xf <= (float)(IW - 1)) ? 1.f : 0.f;
    float v1 = (xf >= -1.f && xf <= (float)(IW - 2)) ? 1.f : 0.f;
    BLX b;
    b.o0 = (int)fminf(fmaxf(xf,       0.f), (float)(IW - 1));
    b.o1 = (int)fminf(fmaxf(xf + 1.f, 0.f), (float)(IW - 1));
    b.w0 = (1.f - wx) * v0;
    b.w1 = wx * v1;
    return b;
}

__device__ __forceinline__ float samp2(const float* __restrict__ p, const BLX& b) {
    return __ldg(p + b.o0) * b.w0 + __ldg(p + b.o1) * b.w1;
}

// ---------------- main kernel ----------------
// One thread handles pixel (h, w) at depths d and d+32, both batches: 4 outputs.
__global__ void __launch_bounds__(IW)
volume_kernel(const float* __restrict__ left,
              const float* __restrict__ right,
              float* __restrict__ out) {
    int w  = threadIdx.x;
    int h  = blockIdx.x;
    int d  = blockIdx.y;               // 0..31; second slice is d+32
    int idx = (d * IH + h) * IW + w;   // flat index for slice 0

    // noise lanes: [0] = (b0, d), [1] = (b0, d+32), [2] = (b1, d), [3] = (b1, d+32)
    uint32_t lo[4];
    lo[0] = (uint32_t)idx;
    lo[1] = (uint32_t)(idx + DSTRIDE);
    lo[2] = (uint32_t)(idx + DHW);
    lo[3] = (uint32_t)(idx + DHW + DSTRIDE);
    float n[4];
    tf_uniform4(lo, n);

    const float inv_max = (float)(1.0 / 40.0);
    const float scale   = (float)(1.0 / 10.0 - 1.0 / 40.0);
    float d0f = (float)d;
    float d1f = (float)(d + ND2);
    // q = inverse depth (the reference's pre-reciprocal value)
    float q[4];
    q[0] = inv_max + ((n[0] + d0f) * (1.0f / 64.0f)) * scale;
    q[1] = inv_max + ((n[1] + d1f) * (1.0f / 64.0f)) * scale;
    q[2] = inv_max + ((n[2] + d0f) * (1.0f / 64.0f)) * scale;
    q[3] = inv_max + ((n[3] + d1f) * (1.0f / 64.0f)) * scale;

    float xs = (float)w;
    int rowoff = h * IW;

    if (__ldg(&g_fast)) {
        float t0l0 = __ldg(&g_mats[0 * 12 + 9]);   // left,  b=0
        float t0l1 = __ldg(&g_mats[1 * 12 + 9]);   // left,  b=1
        float t0r0 = __ldg(&g_mats[2 * 12 + 9]);   // right, b=0
        float t0r1 = __ldg(&g_mats[3 * 12 + 9]);   // right, b=1

#pragma unroll
        for (int k = 0; k < 4; k++) {
            int b = k >> 1;              // lane 0,1 -> b=0 ; lane 2,3 -> b=1
            float t0l = b ? t0l1 : t0l0;
            float t0r = b ? t0r1 : t0r0;
            BLX bl = mkblx(fmaf(t0l, q[k], xs));
            BLX br = mkblx(fmaf(t0r, q[k], xs));

            const float* Lrow = left  + b * CHW + rowoff;
            const float* Rrow = right + b * CHW + rowoff;
            float acc = 0.f;
#pragma unroll
            for (int c = 0; c < 3; c++) {
                float lv = samp2(Lrow + c * HW, bl);
                float rv = samp2(Rrow + c * HW, br);
                acc += fabsf(rv - lv);
            }
            int dslice = (k & 1) ? DSTRIDE : 0;
            out[b * DHW + dslice + idx] = acc;
        }
    } else {
        float ys = (float)h;
#pragma unroll
        for (int k = 0; k < 4; k++) {
            int b = k >> 1;
            float depth = __frcp_rn(q[k]);
            const float* Lb = left  + b * CHW;
            const float* Rb = right + b * CHW;

            float pxl, pyl, pxr, pyr;
            project(g_mats + (0 * 2 + b) * 12, xs, ys, depth, pxl, pyl);
            project(g_mats + (1 * 2 + b) * 12, xs, ys, depth, pxr, pyr);

            BL bl = mkbl(pxl, pyl);
            BL br = mkbl(pxr, pyr);

            float acc = 0.f;
#pragma unroll
            for (int c = 0; c < 3; c++) {
                float lv = samp(Lb + c * HW, bl);
                float rv = samp(Rb + c * HW, br);
                acc += fabsf(rv - lv);
            }
            int dslice = (k & 1) ? DSTRIDE : 0;
            out[b * DHW + dslice + idx] = acc;
        }
    }
}

// ---------------- launch ----------------
extern "C" void kernel_launch(void* const* d_in, const int* in_sizes, int n_in,
                              void* d_out, int out_size) {
    const float* left  = (const float*)d_in[0];
    const float* right = (const float*)d_in[1];
    const float* lp    = (const float*)d_in[2];
    const float* rp    = (const float*)d_in[3];
    const float* gp    = (const float*)d_in[4];

    setup_kernel<<<1, 64>>>(lp, rp, gp);
    dim3 grid(IH, ND2);
    volume_kernel<<<grid, IW>>>(left, right, (float*)d_out);
}

// round 12
// speedup vs baseline: 1.0113x; 1.0113x over previous
#include <cuda_runtime.h>
#include <cstdint>

#define IW 320
#define IH 256
#define ND 64
#define NB 2
#define HW (IH*IW)          // 81920
#define DHW (ND*IH*IW)      // 5242880
#define CHW (3*HW)
#define ND2 (ND/2)          // 32
#define DSTRIDE (ND2*IH*IW) // offset between the two depth slices

// [side(2)][batch(2)][12: r00..r22, t0,t1,t2]
__device__ float g_mats[48];
__device__ int   g_fast;     // 1 => rot==I, t1==t2==0 for all 4 mats

// ---------------- setup: proj = src_proj @ inv(gt_proj), parallel ----------------
__global__ void setup_kernel(const float* __restrict__ lp,
                             const float* __restrict__ rp,
                             const float* __restrict__ gp) {
    __shared__ double sinv[2][16];
    __shared__ float smats[48];
    int t = threadIdx.x;

    if (t < 2) {
        double m[16];
        const float* G = gp + 16 * t;
#pragma unroll
        for (int i = 0; i < 16; i++) m[i] = (double)G[i];
        double v[16];
        v[0]  =  m[5]*m[10]*m[15] - m[5]*m[11]*m[14] - m[9]*m[6]*m[15] + m[9]*m[7]*m[14] + m[13]*m[6]*m[11] - m[13]*m[7]*m[10];
        v[4]  = -m[4]*m[10]*m[15] + m[4]*m[11]*m[14] + m[8]*m[6]*m[15] - m[8]*m[7]*m[14] - m[12]*m[6]*m[11] + m[12]*m[7]*m[10];
        v[8]  =  m[4]*m[9]*m[15]  - m[4]*m[11]*m[13] - m[8]*m[5]*m[15] + m[8]*m[7]*m[13] + m[12]*m[5]*m[11] - m[12]*m[7]*m[9];
        v[12] = -m[4]*m[9]*m[14]  + m[4]*m[10]*m[13] + m[8]*m[5]*m[14] - m[8]*m[6]*m[13] - m[12]*m[5]*m[10] + m[12]*m[6]*m[9];
        v[1]  = -m[1]*m[10]*m[15] + m[1]*m[11]*m[14] + m[9]*m[2]*m[15] - m[9]*m[3]*m[14] - m[13]*m[2]*m[11] + m[13]*m[3]*m[10];
        v[5]  =  m[0]*m[10]*m[15] - m[0]*m[11]*m[14] - m[8]*m[2]*m[15] + m[8]*m[3]*m[14] + m[12]*m[2]*m[11] - m[12]*m[3]*m[10];
        v[9]  = -m[0]*m[9]*m[15]  + m[0]*m[11]*m[13] + m[8]*m[1]*m[15] - m[8]*m[3]*m[13] - m[12]*m[1]*m[11] + m[12]*m[3]*m[9];
        v[13] =  m[0]*m[9]*m[14]  - m[0]*m[10]*m[13] - m[8]*m[1]*m[14] + m[8]*m[2]*m[13] + m[12]*m[1]*m[10] - m[12]*m[2]*m[9];
        v[2]  =  m[1]*m[6]*m[15]  - m[1]*m[7]*m[14]  - m[5]*m[2]*m[15] + m[5]*m[3]*m[14] + m[13]*m[2]*m[7]  - m[13]*m[3]*m[6];
        v[6]  = -m[0]*m[6]*m[15]  + m[0]*m[7]*m[14]  + m[4]*m[2]*m[15] - m[4]*m[3]*m[14] - m[12]*m[2]*m[7]  + m[12]*m[3]*m[6];
        v[10] =  m[0]*m[5]*m[15]  - m[0]*m[7]*m[13]  - m[4]*m[1]*m[15] + m[4]*m[3]*m[13] + m[12]*m[1]*m[7]  - m[12]*m[3]*m[5];
        v[14] = -m[0]*m[5]*m[14]  + m[0]*m[6]*m[13]  + m[4]*m[1]*m[14] - m[4]*m[2]*m[13] - m[12]*m[1]*m[6]  + m[12]*m[2]*m[5];
        v[3]  = -m[1]*m[6]*m[11]  + m[1]*m[7]*m[10]  + m[5]*m[2]*m[11] - m[5]*m[3]*m[10] - m[9]*m[2]*m[7]   + m[9]*m[3]*m[6];
        v[7]  =  m[0]*m[6]*m[11]  - m[0]*m[7]*m[10]  - m[4]*m[2]*m[11] + m[4]*m[3]*m[10] + m[8]*m[2]*m[7]   - m[8]*m[3]*m[6];
        v[11] = -m[0]*m[5]*m[11]  + m[0]*m[7]*m[9]   + m[4]*m[1]*m[11] - m[4]*m[3]*m[9]  - m[8]*m[1]*m[7]   + m[8]*m[3]*m[5];
        v[15] =  m[0]*m[5]*m[10]  - m[0]*m[6]*m[9]   - m[4]*m[1]*m[10] + m[4]*m[2]*m[9]  + m[8]*m[1]*m[6]   - m[8]*m[2]*m[5];
        double det = m[0]*v[0] + m[1]*v[4] + m[2]*v[8] + m[3]*v[12];
        double rdet = 1.0 / det;
#pragma unroll
        for (int i = 0; i < 16; i++) sinv[t][i] = v[i] * rdet;
    }
    __syncthreads();

    if (t < 48) {
        int mt = t / 12;              // 0..3 = s*2 + b
        int e  = t % 12;
        int s  = mt >> 1, b = mt & 1;
        const float* S = (s == 0 ? lp : rp) + 16 * b;
        int i = (e < 9) ? (e / 3) : (e - 9);
        int j = (e < 9) ? (e % 3) : 3;
        double acc = 0.0;
#pragma unroll
        for (int k = 0; k < 4; k++) acc += (double)S[i * 4 + k] * sinv[b][k * 4 + j];
        float f = (float)acc;
        g_mats[mt * 12 + e] = f;
        smats[mt * 12 + e]  = f;
    }
    __syncthreads();

    if (t == 0) {
        int fast = 1;
        for (int mm = 0; mm < 4; mm++) {
            const float* dd = smats + mm * 12;
            for (int i = 0; i < 3; i++)
                for (int j = 0; j < 3; j++) {
                    float want = (i == j) ? 1.0f : 0.0f;
                    if (fabsf(dd[i * 3 + j] - want) > 1e-4f) fast = 0;
                }
            if (fabsf(dd[10]) > 1e-4f || fabsf(dd[11]) > 1e-4f) fast = 0;
        }
        g_fast = fast;
    }
}

// ---------------- threefry: 4 independent chains, hand-interleaved ----------------
__device__ __forceinline__ uint32_t rotl32(uint32_t x, int d) {
    return __funnelshift_l(x, x, d);
}

// JAX partitionable threefry-2x32, key (0,1), counts (0, lo[i]); output = x0 ^ x1.
__device__ __forceinline__ void tf_uniform4(const uint32_t lo[4], float n[4]) {
    const uint32_t ks2 = 0x1BD11BDBu;
    uint32_t a0, a1, a2, a3;        // x0 lanes
    uint32_t b0, b1, b2, b3;        // x1 lanes
    a0 = 0u; b0 = lo[0] + 1u;
    a1 = 0u; b1 = lo[1] + 1u;
    a2 = 0u; b2 = lo[2] + 1u;
    a3 = 0u; b3 = lo[3] + 1u;
#define TF_R(D)                                              \
    a0 += b0; b0 = rotl32(b0, D); b0 ^= a0;                  \
    a1 += b1; b1 = rotl32(b1, D); b1 ^= a1;                  \
    a2 += b2; b2 = rotl32(b2, D); b2 ^= a2;                  \
    a3 += b3; b3 = rotl32(b3, D); b3 ^= a3;
#define TF_INJ(KA, KB)                                       \
    a0 += (KA); b0 += (KB);                                  \
    a1 += (KA); b1 += (KB);                                  \
    a2 += (KA); b2 += (KB);                                  \
    a3 += (KA); b3 += (KB);
    TF_R(13) TF_R(15) TF_R(26) TF_R(6)   TF_INJ(1u,  ks2 + 1u)
    TF_R(17) TF_R(29) TF_R(16) TF_R(24)  TF_INJ(ks2, 2u)
    TF_R(13) TF_R(15) TF_R(26) TF_R(6)   TF_INJ(0u,  1u + 3u)
    TF_R(17) TF_R(29) TF_R(16) TF_R(24)  TF_INJ(1u,  ks2 + 4u)
    TF_R(13) TF_R(15) TF_R(26) TF_R(6)   TF_INJ(ks2, 5u)
#undef TF_R
#undef TF_INJ
    uint32_t r0 = a0 ^ b0, r1 = a1 ^ b1, r2 = a2 ^ b2, r3 = a3 ^ b3;
    // (r >> 9) via IMAD.HI on the FMA pipe instead of SHF on the ALU pipe
    uint32_t s0 = __umulhi(r0, 1u << 23) | 0x3F800000u;
    uint32_t s1 = __umulhi(r1, 1u << 23) | 0x3F800000u;
    uint32_t s2 = __umulhi(r2, 1u << 23) | 0x3F800000u;
    uint32_t s3 = __umulhi(r3, 1u << 23) | 0x3F800000u;
    n[0] = __uint_as_float(s0) - 1.0f;
    n[1] = __uint_as_float(s1) - 1.0f;
    n[2] = __uint_as_float(s2) - 1.0f;
    n[3] = __uint_as_float(s3) - 1.0f;
}

// ---------------- generic-path helpers ----------------
struct BL {
    int   o00, o10, o01, o11;
    float w00, w10, w01, w11;
};

__device__ __forceinline__ BL mkbl(float px, float py) {
    float x0f = floorf(px), y0f = floorf(py);
    float wx = px - x0f, wy = py - y0f;
    float vx0 = (x0f >= 0.f        && x0f <= (float)(IW - 1)) ? 1.f : 0.f;
    float vx1 = (x0f + 1.f >= 0.f  && x0f + 1.f <= (float)(IW - 1)) ? 1.f : 0.f;
    float vy0 = (y0f >= 0.f        && y0f <= (float)(IH - 1)) ? 1.f : 0.f;
    float vy1 = (y0f + 1.f >= 0.f  && y0f + 1.f <= (float)(IH - 1)) ? 1.f : 0.f;
    int xi0 = (int)fminf(fmaxf(x0f,       0.f), (float)(IW - 1));
    int xi1 = (int)fminf(fmaxf(x0f + 1.f, 0.f), (float)(IW - 1));
    int yi0 = (int)fminf(fmaxf(y0f,       0.f), (float)(IH - 1));
    int yi1 = (int)fminf(fmaxf(y0f + 1.f, 0.f), (float)(IH - 1));
    BL b;
    b.o00 = yi0 * IW + xi0; b.o10 = yi0 * IW + xi1;
    b.o01 = yi1 * IW + xi0; b.o11 = yi1 * IW + xi1;
    b.w00 = (1.f - wx) * (1.f - wy) * vx0 * vy0;
    b.w10 = wx * (1.f - wy) * vx1 * vy0;
    b.w01 = (1.f - wx) * wy * vx0 * vy1;
    b.w11 = wx * wy * vx1 * vy1;
    return b;
}

__device__ __forceinline__ float samp(const float* __restrict__ p, const BL& b) {
    return __ldg(p + b.o00) * b.w00 + __ldg(p + b.o10) * b.w10 +
           __ldg(p + b.o01) * b.w01 + __ldg(p + b.o11) * b.w11;
}

__device__ __forceinline__ void project(const float* M, float x, float y, float depth,
                                        float& px, float& py) {
    float rx = __ldg(M+0) * x + __ldg(M+1) * y + __ldg(M+2);
    float ry = __ldg(M+3) * x + __ldg(M+4) * y + __ldg(M+5);
    float rz = __ldg(M+6) * x + __ldg(M+7) * y + __ldg(M+8);
    float zz = rz * depth + __ldg(M+11);
    bool neg = (zz <= 0.001f);
    float z  = neg ? 1.0f : zz;
    float ax = neg ? (float)IW : (rx * depth + __ldg(M+9));
    float ay = neg ? (float)IH : (ry * depth + __ldg(M+10));
    px = ax / z;
    py = ay / z;
}

// ---------------- fast-path helper: 2-tap horizontal ----------------
struct BLX { int o0, o1; float w0, w1; };

__device__ __forceinline__ BLX mkblx(float px) {
    float xf = floorf(px);
    float wx = px - xf;
    float v0 = (xf >= 0.f  && xf <= (float)(IW - 1)) ? 1.f : 0.f;
    float v1 = (xf >= -1.f && xf <= (float)(IW - 2)) ? 1.f : 0.f;
    BLX b;
    b.o0 = (int)fminf(fmaxf(xf,       0.f), (float)(IW - 1));
    b.o1 = (int)fminf(fmaxf(xf + 1.f, 0.f), (float)(IW - 1));
    b.w0 = (1.f - wx) * v0;
    b.w1 = wx * v1;
    return b;
}

__device__ __forceinline__ float samp2(const float* __restrict__ p, const BLX& b) {
    return __ldg(p + b.o0) * b.w0 + __ldg(p + b.o1) * b.w1;
}

// ---------------- main kernel ----------------
// One thread handles pixel (h, w) at depths d and d+32, both batches: 4 outputs.
// launch_bounds(IW, 4): allow up to ~51 regs so the 4 threefry chains stay
// live in registers and interleave (at 32 regs ptxas serializes them).
__global__ void __launch_bounds__(IW, 4)
volume_kernel(const float* __restrict__ left,
              const float* __restrict__ right,
              float* __restrict__ out) {
    int w  = threadIdx.x;
    int h  = blockIdx.x;
    int d  = blockIdx.y;               // 0..31; second slice is d+32
    int idx = (d * IH + h) * IW + w;   // flat index for slice 0

    // noise lanes: [0] = (b0, d), [1] = (b0, d+32), [2] = (b1, d), [3] = (b1, d+32)
    uint32_t lo[4];
    lo[0] = (uint32_t)idx;
    lo[1] = (uint32_t)(idx + DSTRIDE);
    lo[2] = (uint32_t)(idx + DHW);
    lo[3] = (uint32_t)(idx + DHW + DSTRIDE);
    float n[4];
    tf_uniform4(lo, n);

    const float inv_max = (float)(1.0 / 40.0);
    const float scale   = (float)(1.0 / 10.0 - 1.0 / 40.0);
    float d0f = (float)d;
    float d1f = (float)(d + ND2);
    // q = inverse depth (the reference's pre-reciprocal value)
    float q[4];
    q[0] = inv_max + ((n[0] + d0f) * (1.0f / 64.0f)) * scale;
    q[1] = inv_max + ((n[1] + d1f) * (1.0f / 64.0f)) * scale;
    q[2] = inv_max + ((n[2] + d0f) * (1.0f / 64.0f)) * scale;
    q[3] = inv_max + ((n[3] + d1f) * (1.0f / 64.0f)) * scale;

    float xs = (float)w;
    int rowoff = h * IW;

    if (__ldg(&g_fast)) {
        float t0l0 = __ldg(&g_mats[0 * 12 + 9]);   // left,  b=0
        float t0l1 = __ldg(&g_mats[1 * 12 + 9]);   // left,  b=1
        float t0r0 = __ldg(&g_mats[2 * 12 + 9]);   // right, b=0
        float t0r1 = __ldg(&g_mats[3 * 12 + 9]);   // right, b=1

#pragma unroll
        for (int k = 0; k < 4; k++) {
            int b = k >> 1;              // lane 0,1 -> b=0 ; lane 2,3 -> b=1
            float t0l = b ? t0l1 : t0l0;
            float t0r = b ? t0r1 : t0r0;
            BLX bl = mkblx(fmaf(t0l, q[k], xs));
            BLX br = mkblx(fmaf(t0r, q[k], xs));

            const float* Lrow = left  + b * CHW + rowoff;
            const float* Rrow = right + b * CHW + rowoff;
            float acc = 0.f;
#pragma unroll
            for (int c = 0; c < 3; c++) {
                float lv = samp2(Lrow + c * HW, bl);
                float rv = samp2(Rrow + c * HW, br);
                acc += fabsf(rv - lv);
            }
            int dslice = (k & 1) ? DSTRIDE : 0;
            out[b * DHW + dslice + idx] = acc;
        }
    } else {
        float ys = (float)h;
#pragma unroll
        for (int k = 0; k < 4; k++) {
            int b = k >> 1;
            float depth = __frcp_rn(q[k]);
            const float* Lb = left  + b * CHW;
            const float* Rb = right + b * CHW;

            float pxl, pyl, pxr, pyr;
            project(g_mats + (0 * 2 + b) * 12, xs, ys, depth, pxl, pyl);
            project(g_mats + (1 * 2 + b) * 12, xs, ys, depth, pxr, pyr);

            BL bl = mkbl(pxl, pyl);
            BL br = mkbl(pxr, pyr);

            float acc = 0.f;
#pragma unroll
            for (int c = 0; c < 3; c++) {
                float lv = samp(Lb + c * HW, bl);
                float rv = samp(Rb + c * HW, br);
                acc += fabsf(rv - lv);
            }
            int dslice = (k & 1) ? DSTRIDE : 0;
            out[b * DHW + dslice + idx] = acc;
        }
    }
}

// ---------------- launch ----------------
extern "C" void kernel_launch(void* const* d_in, const int* in_sizes, int n_in,
                              void* d_out, int out_size) {
    const float* left  = (const float*)d_in[0];
    const float* right = (const float*)d_in[1];
    const float* lp    = (const float*)d_in[2];
    const float* rp    = (const float*)d_in[3];
    const float* gp    = (const float*)d_in[4];

    setup_kernel<<<1, 64>>>(lp, rp, gp);
    dim3 grid(IH, ND2);
    volume_kernel<<<grid, IW>>>(left, right, (float*)d_out);
}

// round 14
// speedup vs baseline: 1.0591x; 1.0473x over previous
#include <cuda_runtime.h>
#include <cstdint>

#define IW 320
#define IH 256
#define ND 64
#define NB 2
#define HW (IH*IW)          // 81920
#define DHW (ND*IH*IW)      // 5242880
#define CHW (3*HW)

// [side(2)][batch(2)][12: r00..r22, t0,t1,t2]
__device__ float g_mats[48];
__device__ int   g_fast;     // 1 => rot==I, t1==t2==0 for all 4 mats

// ---------------- setup: proj = src_proj @ inv(gt_proj), parallel ----------------
__global__ void setup_kernel(const float* __restrict__ lp,
                             const float* __restrict__ rp,
                             const float* __restrict__ gp) {
    __shared__ double sinv[2][16];
    __shared__ float smats[48];
    int t = threadIdx.x;

    if (t < 2) {
        double m[16];
        const float* G = gp + 16 * t;
#pragma unroll
        for (int i = 0; i < 16; i++) m[i] = (double)G[i];
        double v[16];
        v[0]  =  m[5]*m[10]*m[15] - m[5]*m[11]*m[14] - m[9]*m[6]*m[15] + m[9]*m[7]*m[14] + m[13]*m[6]*m[11] - m[13]*m[7]*m[10];
        v[4]  = -m[4]*m[10]*m[15] + m[4]*m[11]*m[14] + m[8]*m[6]*m[15] - m[8]*m[7]*m[14] - m[12]*m[6]*m[11] + m[12]*m[7]*m[10];
        v[8]  =  m[4]*m[9]*m[15]  - m[4]*m[11]*m[13] - m[8]*m[5]*m[15] + m[8]*m[7]*m[13] + m[12]*m[5]*m[11] - m[12]*m[7]*m[9];
        v[12] = -m[4]*m[9]*m[14]  + m[4]*m[10]*m[13] + m[8]*m[5]*m[14] - m[8]*m[6]*m[13] - m[12]*m[5]*m[10] + m[12]*m[6]*m[9];
        v[1]  = -m[1]*m[10]*m[15] + m[1]*m[11]*m[14] + m[9]*m[2]*m[15] - m[9]*m[3]*m[14] - m[13]*m[2]*m[11] + m[13]*m[3]*m[10];
        v[5]  =  m[0]*m[10]*m[15] - m[0]*m[11]*m[14] - m[8]*m[2]*m[15] + m[8]*m[3]*m[14] + m[12]*m[2]*m[11] - m[12]*m[3]*m[10];
        v[9]  = -m[0]*m[9]*m[15]  + m[0]*m[11]*m[13] + m[8]*m[1]*m[15] - m[8]*m[3]*m[13] - m[12]*m[1]*m[11] + m[12]*m[3]*m[9];
        v[13] =  m[0]*m[9]*m[14]  - m[0]*m[10]*m[13] - m[8]*m[1]*m[14] + m[8]*m[2]*m[13] + m[12]*m[1]*m[10] - m[12]*m[2]*m[9];
        v[2]  =  m[1]*m[6]*m[15]  - m[1]*m[7]*m[14]  - m[5]*m[2]*m[15] + m[5]*m[3]*m[14] + m[13]*m[2]*m[7]  - m[13]*m[3]*m[6];
        v[6]  = -m[0]*m[6]*m[15]  + m[0]*m[7]*m[14]  + m[4]*m[2]*m[15] - m[4]*m[3]*m[14] - m[12]*m[2]*m[7]  + m[12]*m[3]*m[6];
        v[10] =  m[0]*m[5]*m[15]  - m[0]*m[7]*m[13]  - m[4]*m[1]*m[15] + m[4]*m[3]*m[13] + m[12]*m[1]*m[7]  - m[12]*m[3]*m[5];
        v[14] = -m[0]*m[5]*m[14]  + m[0]*m[6]*m[13]  + m[4]*m[1]*m[14] - m[4]*m[2]*m[13] - m[12]*m[1]*m[6]  + m[12]*m[2]*m[5];
        v[3]  = -m[1]*m[6]*m[11]  + m[1]*m[7]*m[10]  + m[5]*m[2]*m[11] - m[5]*m[3]*m[10] - m[9]*m[2]*m[7]   + m[9]*m[3]*m[6];
        v[7]  =  m[0]*m[6]*m[11]  - m[0]*m[7]*m[10]  - m[4]*m[2]*m[11] + m[4]*m[3]*m[10] + m[8]*m[2]*m[7]   - m[8]*m[3]*m[6];
        v[11] = -m[0]*m[5]*m[11]  + m[0]*m[7]*m[9]   + m[4]*m[1]*m[11] - m[4]*m[3]*m[9]  - m[8]*m[1]*m[7]   + m[8]*m[3]*m[5];
        v[15] =  m[0]*m[5]*m[10]  - m[0]*m[6]*m[9]   - m[4]*m[1]*m[10] + m[4]*m[2]*m[9]  + m[8]*m[1]*m[6]   - m[8]*m[2]*m[5];
        double det = m[0]*v[0] + m[1]*v[4] + m[2]*v[8] + m[3]*v[12];
        double rdet = 1.0 / det;
#pragma unroll
        for (int i = 0; i < 16; i++) sinv[t][i] = v[i] * rdet;
    }
    __syncthreads();

    if (t < 48) {
        int mt = t / 12;              // 0..3 = s*2 + b
        int e  = t % 12;
        int s  = mt >> 1, b = mt & 1;
        const float* S = (s == 0 ? lp : rp) + 16 * b;
        int i = (e < 9) ? (e / 3) : (e - 9);
        int j = (e < 9) ? (e % 3) : 3;
        double acc = 0.0;
#pragma unroll
        for (int k = 0; k < 4; k++) acc += (double)S[i * 4 + k] * sinv[b][k * 4 + j];
        float f = (float)acc;
        g_mats[mt * 12 + e] = f;
        smats[mt * 12 + e]  = f;
    }
    __syncthreads();

    if (t == 0) {
        int fast = 1;
        for (int mm = 0; mm < 4; mm++) {
            const float* dd = smats + mm * 12;
            for (int i = 0; i < 3; i++)
                for (int j = 0; j < 3; j++) {
                    float want = (i == j) ? 1.0f : 0.0f;
                    if (fabsf(dd[i * 3 + j] - want) > 1e-4f) fast = 0;
                }
            if (fabsf(dd[10]) > 1e-4f || fabsf(dd[11]) > 1e-4f) fast = 0;
        }
        g_fast = fast;
    }
}

// ---------------- threefry: 2 independent chains, hand-interleaved ----------------
__device__ __forceinline__ uint32_t rotl32(uint32_t x, int d) {
    return __funnelshift_l(x, x, d);
}

// JAX partitionable threefry-2x32, key (0,1), counts (0, lo); output = x0 ^ x1.
// Returns u in [1,2): uniform = u - 1 (caller folds the -1 into its add).
__device__ __forceinline__ void tf_uniform2(uint32_t l0, uint32_t l1,
                                            float& u0, float& u1) {
    const uint32_t ks2 = 0x1BD11BDBu;
    uint32_t a0 = 0u, b0 = l0 + 1u;
    uint32_t a1 = 0u, b1 = l1 + 1u;
#define TF_R(D)                                    \
    a0 += b0; b0 = rotl32(b0, D); b0 ^= a0;        \
    a1 += b1; b1 = rotl32(b1, D); b1 ^= a1;
#define TF_INJ(KA, KB)                             \
    a0 += (KA); b0 += (KB);                        \
    a1 += (KA); b1 += (KB);
    TF_R(13) TF_R(15) TF_R(26) TF_R(6)   TF_INJ(1u,  ks2 + 1u)
    TF_R(17) TF_R(29) TF_R(16) TF_R(24)  TF_INJ(ks2, 2u)
    TF_R(13) TF_R(15) TF_R(26) TF_R(6)   TF_INJ(0u,  1u + 3u)
    TF_R(17) TF_R(29) TF_R(16) TF_R(24)  TF_INJ(1u,  ks2 + 4u)
    TF_R(13) TF_R(15) TF_R(26) TF_R(6)   TF_INJ(ks2, 5u)
#undef TF_R
#undef TF_INJ
    uint32_t r0 = a0 ^ b0, r1 = a1 ^ b1;
    // (r >> 9) via IMAD.HI (fma pipe) instead of SHF (alu pipe)
    u0 = __uint_as_float(__umulhi(r0, 1u << 23) | 0x3F800000u);
    u1 = __uint_as_float(__umulhi(r1, 1u << 23) | 0x3F800000u);
}

// ---------------- generic-path helpers ----------------
struct BL {
    int   o00, o10, o01, o11;
    float w00, w10, w01, w11;
};

__device__ __forceinline__ BL mkbl(float px, float py) {
    float x0f = floorf(px), y0f = floorf(py);
    float wx = px - x0f, wy = py - y0f;
    float vx0 = (x0f >= 0.f        && x0f <= (float)(IW - 1)) ? 1.f : 0.f;
    float vx1 = (x0f + 1.f >= 0.f  && x0f + 1.f <= (float)(IW - 1)) ? 1.f : 0.f;
    float vy0 = (y0f >= 0.f        && y0f <= (float)(IH - 1)) ? 1.f : 0.f;
    float vy1 = (y0f + 1.f >= 0.f  && y0f + 1.f <= (float)(IH - 1)) ? 1.f : 0.f;
    int xi0 = (int)fminf(fmaxf(x0f,       0.f), (float)(IW - 1));
    int xi1 = (int)fminf(fmaxf(x0f + 1.f, 0.f), (float)(IW - 1));
    int yi0 = (int)fminf(fmaxf(y0f,       0.f), (float)(IH - 1));
    int yi1 = (int)fminf(fmaxf(y0f + 1.f, 0.f), (float)(IH - 1));
    BL b;
    b.o00 = yi0 * IW + xi0; b.o10 = yi0 * IW + xi1;
    b.o01 = yi1 * IW + xi0; b.o11 = yi1 * IW + xi1;
    b.w00 = (1.f - wx) * (1.f - wy) * vx0 * vy0;
    b.w10 = wx * (1.f - wy) * vx1 * vy0;
    b.w01 = (1.f - wx) * wy * vx0 * vy1;
    b.w11 = wx * wy * vx1 * vy1;
    return b;
}

__device__ __forceinline__ float samp(const float* __restrict__ p, const BL& b) {
    return __ldg(p + b.o00) * b.w00 + __ldg(p + b.o10) * b.w10 +
           __ldg(p + b.o01) * b.w01 + __ldg(p + b.o11) * b.w11;
}

__device__ __forceinline__ void project(const float* M, float x, float y, float depth,
                                        float& px, float& py) {
    float rx = __ldg(M+0) * x + __ldg(M+1) * y + __ldg(M+2);
    float ry = __ldg(M+3) * x + __ldg(M+4) * y + __ldg(M+5);
    float rz = __ldg(M+6) * x + __ldg(M+7) * y + __ldg(M+8);
    float zz = rz * depth + __ldg(M+11);
    bool neg = (zz <= 0.001f);
    float z  = neg ? 1.0f : zz;
    float ax = neg ? (float)IW : (rx * depth + __ldg(M+9));
    float ay = neg ? (float)IH : (ry * depth + __ldg(M+10));
    px = ax / z;
    py = ay / z;
}

// ---------------- fast-path: sign-specialized 2-tap horizontal ----------------
struct BLX { int o0, o1; float w0, w1; };

// t0 > 0: px >= x >= 0 always -> only the upper bound can trip.
__device__ __forceinline__ BLX mkblx_hi(float px) {
    float xf = floorf(px);
    float wx = px - xf;
    int   xi = (int)xf;
    BLX b;
    b.o0 = min(xi,     IW - 1);
    b.o1 = min(xi + 1, IW - 1);
    b.w0 = (xf <= (float)(IW - 1)) ? (1.f - wx) : 0.f;
    b.w1 = (xf <= (float)(IW - 2)) ? wx         : 0.f;
    return b;
}

// t0 < 0: px <= x <= IW-1 always -> only the lower bound can trip.
__device__ __forceinline__ BLX mkblx_lo(float px) {
    float xf = floorf(px);
    float wx = px - xf;
    int   xi = (int)xf;
    BLX b;
    b.o0 = max(xi,     0);
    b.o1 = max(xi + 1, 0);
    b.w0 = (xf >=  0.f) ? (1.f - wx) : 0.f;
    b.w1 = (xf >= -1.f) ? wx         : 0.f;
    return b;
}

__device__ __forceinline__ BLX mkblx_signed(float px, bool pos) {
    // pos is warp-uniform (sign of t0 for this side/batch)
    return pos ? mkblx_hi(px) : mkblx_lo(px);
}

__device__ __forceinline__ float samp2(const float* __restrict__ p, const BLX& b) {
    return __ldg(p + b.o0) * b.w0 + __ldg(p + b.o1) * b.w1;
}

// ---------------- main kernel: one block = one image row at one depth ----------------
__global__ void __launch_bounds__(IW)
volume_kernel(const float* __restrict__ left,
              const float* __restrict__ right,
              float* __restrict__ out) {
    int w = threadIdx.x;
    int h = blockIdx.x;
    int d = blockIdx.y;
    int idx = (d * IH + h) * IW + w;

    float u0, u1;    // uniform + 1.0 (fold the -1 into the depth-index add)
    tf_uniform2((uint32_t)idx, (uint32_t)(idx + DHW), u0, u1);

    const float inv_max = (float)(1.0 / 40.0);
    const float scale   = (float)(1.0 / 10.0 - 1.0 / 40.0);
    float dm1 = (float)d - 1.0f;
    // s = (u-1) + d == u + (d-1) (same exact real, single rounding each)
    float q0 = inv_max + ((u0 + dm1) * (1.0f / 64.0f)) * scale;
    float q1 = inv_max + ((u1 + dm1) * (1.0f / 64.0f)) * scale;

    float xs = (float)w;
    int rowoff = h * IW;

    if (__ldg(&g_fast)) {
#pragma unroll
        for (int b = 0; b < NB; b++) {
            float q   = b ? q1 : q0;
            float t0l = __ldg(&g_mats[(0 * 2 + b) * 12 + 9]);
            float t0r = __ldg(&g_mats[(1 * 2 + b) * 12 + 9]);
            BLX bl = mkblx_signed(fmaf(t0l, q, xs), t0l > 0.f);
            BLX br = mkblx_signed(fmaf(t0r, q, xs), t0r > 0.f);

            const float* Lrow = left  + b * CHW + rowoff;
            const float* Rrow = right + b * CHW + rowoff;
            float acc = 0.f;
#pragma unroll
            for (int c = 0; c < 3; c++) {
                float lv = samp2(Lrow + c * HW, bl);
                float rv = samp2(Rrow + c * HW, br);
                acc += fabsf(rv - lv);
            }
            out[b * DHW + idx] = acc;
        }
    } else {
        float depth0 = __frcp_rn(q0);
        float depth1 = __frcp_rn(q1);
        float ys = (float)h;
#pragma unroll
        for (int b = 0; b < NB; b++) {
            float depth = b ? depth1 : depth0;
            const float* Lb = left  + b * CHW;
            const float* Rb = right + b * CHW;

            float pxl, pyl, pxr, pyr;
            project(g_mats + (0 * 2 + b) * 12, xs, ys, depth, pxl, pyl);
            project(g_mats + (1 * 2 + b) * 12, xs, ys, depth, pxr, pyr);

            BL bl = mkbl(pxl, pyl);
            BL br = mkbl(pxr, pyr);

            float acc = 0.f;
#pragma unroll
            for (int c = 0; c < 3; c++) {
                float lv = samp(Lb + c * HW, bl);
                float rv = samp(Rb + c * HW, br);
                acc += fabsf(rv - lv);
            }
            out[b * DHW + idx] = acc;
        }
    }
}

// ---------------- launch ----------------
extern "C" void kernel_launch(void* const* d_in, const int* in_sizes, int n_in,
                              void* d_out, int out_size) {
    const float* left  = (const float*)d_in[0];
    const float* right = (const float*)d_in[1];
    const float* lp    = (const float*)d_in[2];
    const float* rp    = (const float*)d_in[3];
    const float* gp    = (const float*)d_in[4];

    setup_kernel<<<1, 64>>>(lp, rp, gp);
    dim3 grid(IH, ND);
    volume_kernel<<<grid, IW>>>(left, right, (float*)d_out);
}